// round 3
// baseline (speedup 1.0000x reference)
#include <cuda_runtime.h>

#define SEQ 8192
#define EMB 768
#define DIM 64
#define PAD 68

// Scratch for projected Q (pre-scaled by 1/sqrt(D)), K, V.
__device__ float g_Q[SEQ * DIM];
__device__ float g_K[SEQ * DIM];
__device__ float g_V[SEQ * DIM];

// ---------------------------------------------------------------------------
// Kernel 1: QKV projection. C[8192,64] = X[8192,768] @ W[768,64].
// grid (128, 3): blockIdx.y selects W_Q / W_K / W_V. 256 threads, 4x4 micro.
// ---------------------------------------------------------------------------
__global__ __launch_bounds__(256, 1) void qkv_kernel(
    const float* __restrict__ X,
    const float* __restrict__ WQ,
    const float* __restrict__ WK,
    const float* __restrict__ WV)
{
    __shared__ float Xs[64][17];     // [m][k], padded (scalar reads)
    __shared__ float Ws[16][PAD];    // [k][n], padded for float4

    const int tid = threadIdx.x;
    const int tx = tid & 15;
    const int ty = tid >> 4;
    const int mbase = blockIdx.x * 64;
    const int w = blockIdx.y;
    const float* __restrict__ W = (w == 0) ? WQ : ((w == 1) ? WK : WV);

    const int xr = tid >> 2;          // 0..63
    const int xc = (tid & 3) << 2;    // 0,4,8,12
    const int wr = tid >> 4;          // 0..15
    const int wc = (tid & 15) << 2;   // 0..60

    float acc[4][4];
#pragma unroll
    for (int i = 0; i < 4; i++)
#pragma unroll
        for (int j = 0; j < 4; j++) acc[i][j] = 0.f;

    for (int kb = 0; kb < EMB; kb += 16) {
        float4 xv = *(const float4*)(X + (mbase + xr) * EMB + kb + xc);
        Xs[xr][xc + 0] = xv.x;
        Xs[xr][xc + 1] = xv.y;
        Xs[xr][xc + 2] = xv.z;
        Xs[xr][xc + 3] = xv.w;
        *(float4*)&Ws[wr][wc] = *(const float4*)(W + (kb + wr) * DIM + wc);
        __syncthreads();
#pragma unroll
        for (int k = 0; k < 16; k++) {
            float a[4];
#pragma unroll
            for (int i = 0; i < 4; i++) a[i] = Xs[4 * ty + i][k];
            float4 b4 = *(const float4*)&Ws[k][4 * tx];
            const float* b = (const float*)&b4;
#pragma unroll
            for (int i = 0; i < 4; i++)
#pragma unroll
                for (int j = 0; j < 4; j++) acc[i][j] += a[i] * b[j];
        }
        __syncthreads();
    }

    // Pre-fold the 1/sqrt(D) = 1/8 softmax scale into Q.
    const float scale = (w == 0) ? 0.125f : 1.0f;
    float* dst = (w == 0) ? g_Q : ((w == 1) ? g_K : g_V);
#pragma unroll
    for (int i = 0; i < 4; i++) {
        float4 o4;
        o4.x = acc[i][0] * scale;
        o4.y = acc[i][1] * scale;
        o4.z = acc[i][2] * scale;
        o4.w = acc[i][3] * scale;
        *(float4*)(dst + (mbase + 4 * ty + i) * DIM + 4 * tx) = o4;
    }
}

// ---------------------------------------------------------------------------
// Kernel 2: flash attention, fp32, online softmax.
// grid 128 (BM=64 query rows per block), 256 threads (16x16 layout).
// Thread (ty,tx) owns S/O rows {4*ty+i} and columns {tx + 16*j}.
// Column mapping tx+16j (not 4tx+j) keeps K-row float4 smem loads at
// 2-way instead of 8-way bank conflicts.
// ---------------------------------------------------------------------------
extern __shared__ float smf[];

__global__ __launch_bounds__(256, 1) void attn_kernel(float* __restrict__ out)
{
    float* Qs = smf;                  // [64][PAD]
    float* Ks = smf + 64 * PAD;       // [64][PAD]
    float* Vs = smf + 2 * 64 * PAD;   // [64][PAD]
    float* Ps = smf + 3 * 64 * PAD;   // [64][PAD]

    const int tid = threadIdx.x;
    const int tx = tid & 15;
    const int ty = tid >> 4;
    const int qbase = blockIdx.x * 64;
    const int lr = tid >> 2;          // load row 0..63
    const int lc = (tid & 3) << 4;    // load col 0,16,32,48

#pragma unroll
    for (int u = 0; u < 4; u++)
        *(float4*)&Qs[lr * PAD + lc + 4 * u] =
            *(const float4*)(g_Q + (qbase + lr) * DIM + lc + 4 * u);

    float m[4], l[4], o[4][4];
#pragma unroll
    for (int i = 0; i < 4; i++) {
        m[i] = -1e30f;
        l[i] = 0.f;
#pragma unroll
        for (int j = 0; j < 4; j++) o[i][j] = 0.f;
    }

    for (int nb = 0; nb < SEQ; nb += 64) {
        // --- load K,V tile (64x64 each) ---
#pragma unroll
        for (int u = 0; u < 4; u++) {
            *(float4*)&Ks[lr * PAD + lc + 4 * u] =
                *(const float4*)(g_K + (nb + lr) * DIM + lc + 4 * u);
            *(float4*)&Vs[lr * PAD + lc + 4 * u] =
                *(const float4*)(g_V + (nb + lr) * DIM + lc + 4 * u);
        }
        __syncthreads();

        // --- S = Qs @ Ks^T (Q pre-scaled) ---
        float s[4][4];
#pragma unroll
        for (int i = 0; i < 4; i++)
#pragma unroll
            for (int j = 0; j < 4; j++) s[i][j] = 0.f;

#pragma unroll 4
        for (int d4 = 0; d4 < DIM; d4 += 4) {
            float4 a4[4], b4[4];
#pragma unroll
            for (int i = 0; i < 4; i++)
                a4[i] = *(const float4*)&Qs[(4 * ty + i) * PAD + d4];
#pragma unroll
            for (int j = 0; j < 4; j++)
                b4[j] = *(const float4*)&Ks[(tx + 16 * j) * PAD + d4];
#pragma unroll
            for (int i = 0; i < 4; i++) {
                const float* a = (const float*)&a4[i];
#pragma unroll
                for (int j = 0; j < 4; j++) {
                    const float* b = (const float*)&b4[j];
                    s[i][j] += a[0] * b[0];
                    s[i][j] += a[1] * b[1];
                    s[i][j] += a[2] * b[2];
                    s[i][j] += a[3] * b[3];
                }
            }
        }

        // --- online softmax; rows owned by 16 tx-lanes -> shfl reduce ---
#pragma unroll
        for (int i = 0; i < 4; i++) {
            float tm = fmaxf(fmaxf(s[i][0], s[i][1]), fmaxf(s[i][2], s[i][3]));
            tm = fmaxf(tm, __shfl_xor_sync(0xffffffffu, tm, 1));
            tm = fmaxf(tm, __shfl_xor_sync(0xffffffffu, tm, 2));
            tm = fmaxf(tm, __shfl_xor_sync(0xffffffffu, tm, 4));
            tm = fmaxf(tm, __shfl_xor_sync(0xffffffffu, tm, 8));
            float mnew = fmaxf(m[i], tm);
            float corr = __expf(m[i] - mnew);
            float rs = 0.f;
#pragma unroll
            for (int j = 0; j < 4; j++) {
                s[i][j] = __expf(s[i][j] - mnew);
                rs += s[i][j];
            }
            rs += __shfl_xor_sync(0xffffffffu, rs, 1);
            rs += __shfl_xor_sync(0xffffffffu, rs, 2);
            rs += __shfl_xor_sync(0xffffffffu, rs, 4);
            rs += __shfl_xor_sync(0xffffffffu, rs, 8);
            l[i] = l[i] * corr + rs;
            m[i] = mnew;
#pragma unroll
            for (int j = 0; j < 4; j++) {
                o[i][j] *= corr;
                Ps[(4 * ty + i) * PAD + tx + 16 * j] = s[i][j];
            }
        }
        __syncthreads();

        // --- O += P @ V ---
#pragma unroll 4
        for (int n4 = 0; n4 < 64; n4 += 4) {
            float4 p4[4];
#pragma unroll
            for (int i = 0; i < 4; i++)
                p4[i] = *(const float4*)&Ps[(4 * ty + i) * PAD + n4];
#pragma unroll
            for (int q = 0; q < 4; q++) {
                float v[4];
#pragma unroll
                for (int j = 0; j < 4; j++)
                    v[j] = Vs[(n4 + q) * PAD + tx + 16 * j];
#pragma unroll
                for (int i = 0; i < 4; i++) {
                    const float* p = (const float*)&p4[i];
#pragma unroll
                    for (int j = 0; j < 4; j++)
                        o[i][j] += p[q] * v[j];
                }
            }
        }
        __syncthreads();
    }

    // --- normalize + store ---
#pragma unroll
    for (int i = 0; i < 4; i++) {
        float inv = 1.0f / l[i];
#pragma unroll
        for (int j = 0; j < 4; j++)
            out[(qbase + 4 * ty + i) * DIM + tx + 16 * j] = o[i][j] * inv;
    }
}

// ---------------------------------------------------------------------------
extern "C" void kernel_launch(void* const* d_in, const int* in_sizes, int n_in,
                              void* d_out, int out_size)
{
    const float* X  = (const float*)d_in[0];
    const float* WQ = (const float*)d_in[1];
    const float* WK = (const float*)d_in[2];
    const float* WV = (const float*)d_in[3];
    float* out = (float*)d_out;

    const int smem_bytes = 4 * 64 * PAD * sizeof(float);  // 69632
    cudaFuncSetAttribute(attn_kernel,
                         cudaFuncAttributeMaxDynamicSharedMemorySize,
                         smem_bytes);

    dim3 g1(SEQ / 64, 3);
    qkv_kernel<<<g1, 256>>>(X, WQ, WK, WV);
    attn_kernel<<<SEQ / 64, 256, smem_bytes>>>(out);
}

// round 9
// speedup vs baseline: 3.1674x; 3.1674x over previous
#include <cuda_runtime.h>
#include <cuda_bf16.h>
#include <cstdint>

#define SEQ 8192
#define EMB 768
#define DIM 64
#define BM 128
#define BN 64
#define NSPLIT 2
#define KVPER (SEQ / NSPLIT)
#define NT (KVPER / BN)
#define L2E 1.4426950408889634f
#define ROWB 144   // padded smem row bytes (64 bf16 = 128B data + 16B pad)

__device__ __nv_bfloat16 g_Qh[SEQ * DIM], g_Ql[SEQ * DIM];
__device__ __nv_bfloat16 g_Kh[SEQ * DIM], g_Kl[SEQ * DIM];
__device__ __nv_bfloat16 g_Vh[SEQ * DIM], g_Vl[SEQ * DIM];
__device__ float g_Op[NSPLIT * SEQ * DIM];
__device__ float g_m[NSPLIT * SEQ], g_l[NSPLIT * SEQ];

__device__ __forceinline__ uint32_t smem_u32(const void* p) {
    uint32_t a;
    asm("{ .reg .u64 t; cvta.to.shared.u64 t, %1; cvt.u32.u64 %0, t; }" : "=r"(a) : "l"(p));
    return a;
}
__device__ __forceinline__ float ex2f(float x) {
    float y; asm("ex2.approx.ftz.f32 %0, %1;" : "=f"(y) : "f"(x)); return y;
}
__device__ __forceinline__ void cpa16(uint32_t dst, const void* src) {
    asm volatile("cp.async.cg.shared.global [%0], [%1], 16;" :: "r"(dst), "l"(src));
}
#define CP_COMMIT() asm volatile("cp.async.commit_group;" ::: "memory")
#define CP_WAIT0()  asm volatile("cp.async.wait_group 0;" ::: "memory")

__device__ __forceinline__ uint32_t packbf(float lo, float hi) {
    uint32_t r; asm("cvt.rn.bf16x2.f32 %0, %1, %2;" : "=r"(r) : "f"(hi), "f"(lo)); return r;
}

#define LDSM4(r, a) asm volatile( \
    "ldmatrix.sync.aligned.m8n8.x4.shared.b16 {%0,%1,%2,%3}, [%4];" \
    : "=r"((r)[0]), "=r"((r)[1]), "=r"((r)[2]), "=r"((r)[3]) : "r"(a))
#define LDSM4T(r, a) asm volatile( \
    "ldmatrix.sync.aligned.m8n8.x4.trans.shared.b16 {%0,%1,%2,%3}, [%4];" \
    : "=r"((r)[0]), "=r"((r)[1]), "=r"((r)[2]), "=r"((r)[3]) : "r"(a))
#define MMA(d, a, b0, b1) asm volatile( \
    "mma.sync.aligned.m16n8k16.row.col.f32.bf16.bf16.f32 " \
    "{%0,%1,%2,%3}, {%4,%5,%6,%7}, {%8,%9}, {%0,%1,%2,%3};" \
    : "+f"((d)[0]), "+f"((d)[1]), "+f"((d)[2]), "+f"((d)[3]) \
    : "r"((a)[0]), "r"((a)[1]), "r"((a)[2]), "r"((a)[3]), "r"(b0), "r"(b1))

// smem byte offsets (K/V have 2 buffers of 64*ROWB each)
#define OQH 0
#define OQL (OQH + BM * ROWB)
#define OKH (OQL + BM * ROWB)
#define OKL (OKH + 2 * BN * ROWB)
#define OVH (OKL + 2 * BN * ROWB)
#define OVL (OVH + 2 * BN * ROWB)
#define SMEM_BYTES (OVL + 2 * BN * ROWB)   // 110592

extern __shared__ char dynsm[];

// ---------------------------------------------------------------------------
// Flash attention, FA2-style mma.sync bf16 hi/lo split.
// 256 threads = 8 warps; warp w owns query rows w*16..w*16+15.
// ---------------------------------------------------------------------------
__global__ __launch_bounds__(256, 1) void attn_kernel() {
    const int tid = threadIdx.x, lane = tid & 31, wid = tid >> 5;
    const int qbase = blockIdx.x * BM;
    const int kbase = blockIdx.y * KVPER;
    const uint32_t sb = smem_u32(dynsm);

    // ---- prologue: Q (hi/lo) + K/V tile 0 ----
#pragma unroll
    for (int i = 0; i < 4; i++) {
        int c = tid + i * 256;                         // 0..1023
        uint32_t d = (uint32_t)((c >> 3) * ROWB + (c & 7) * 16);
        size_t sByte = ((size_t)(qbase + (c >> 3)) * DIM) * 2 + (c & 7) * 16;
        cpa16(sb + OQH + d, (const char*)g_Qh + sByte);
        cpa16(sb + OQL + d, (const char*)g_Ql + sByte);
    }
#pragma unroll
    for (int i = 0; i < 2; i++) {
        int c = tid + i * 256;                         // 0..511
        uint32_t d = (uint32_t)((c >> 3) * ROWB + (c & 7) * 16);
        size_t sByte = ((size_t)(kbase + (c >> 3)) * DIM) * 2 + (c & 7) * 16;
        cpa16(sb + OKH + d, (const char*)g_Kh + sByte);
        cpa16(sb + OKL + d, (const char*)g_Kl + sByte);
        cpa16(sb + OVH + d, (const char*)g_Vh + sByte);
        cpa16(sb + OVL + d, (const char*)g_Vl + sByte);
    }
    CP_COMMIT(); CP_WAIT0();
    __syncthreads();

    // ---- Q fragments (register resident): A-frag layout ----
    uint32_t qh[4][4], ql[4][4];
    {
        uint32_t r = (uint32_t)(wid * 16 + (lane & 15));
        uint32_t bo = ((lane >> 4) & 1) << 4;
#pragma unroll
        for (int c = 0; c < 4; c++) {
            LDSM4(qh[c], sb + OQH + r * ROWB + c * 32 + bo);
            LDSM4(ql[c], sb + OQL + r * ROWB + c * 32 + bo);
        }
    }

    float o[8][4];
#pragma unroll
    for (int j = 0; j < 8; j++)
#pragma unroll
        for (int k = 0; k < 4; k++) o[j][k] = 0.f;
    float m0 = -1e30f, m1 = -1e30f, l0 = 0.f, l1 = 0.f;

    // lane-dependent ldmatrix row/byte pieces
    const int krow = (lane & 7) + ((lane & 16) ? 8 : 0);
    const int kbyt = (lane & 8) ? 16 : 0;
    const int vrow = (lane & 7) + ((lane & 8) ? 8 : 0);
    const int vbyt = (lane & 16) ? 16 : 0;

    for (int t = 0; t < NT; t++) {
        const int buf = t & 1, nb = buf ^ 1;
        // ---- prefetch tile t+1 into the other buffer ----
        if (t + 1 < NT) {
            int kr = kbase + (t + 1) * BN;
#pragma unroll
            for (int i = 0; i < 2; i++) {
                int c = tid + i * 256;
                uint32_t d = (uint32_t)(nb * BN * ROWB + (c >> 3) * ROWB + (c & 7) * 16);
                size_t sByte = ((size_t)(kr + (c >> 3)) * DIM) * 2 + (c & 7) * 16;
                cpa16(sb + OKH + d, (const char*)g_Kh + sByte);
                cpa16(sb + OKL + d, (const char*)g_Kl + sByte);
                cpa16(sb + OVH + d, (const char*)g_Vh + sByte);
                cpa16(sb + OVL + d, (const char*)g_Vl + sByte);
            }
            CP_COMMIT();
        }

        // ---- S = Q K^T : qh*kh + ql*kh + qh*kl ----
        float s[8][4];
#pragma unroll
        for (int j = 0; j < 8; j++)
#pragma unroll
            for (int k = 0; k < 4; k++) s[j][k] = 0.f;
        const uint32_t kbH = sb + OKH + buf * BN * ROWB;
        const uint32_t kbL = sb + OKL + buf * BN * ROWB;
#pragma unroll
        for (int c = 0; c < 4; c++) {
#pragma unroll
            for (int p = 0; p < 4; p++) {
                uint32_t b[4], bl[4];
                uint32_t ra = (uint32_t)((p * 16 + krow) * ROWB + c * 32 + kbyt);
                LDSM4(b, kbH + ra);
                LDSM4(bl, kbL + ra);
                MMA(s[2 * p],     qh[c], b[0], b[1]);
                MMA(s[2 * p + 1], qh[c], b[2], b[3]);
                MMA(s[2 * p],     ql[c], b[0], b[1]);
                MMA(s[2 * p + 1], ql[c], b[2], b[3]);
                MMA(s[2 * p],     qh[c], bl[0], bl[1]);
                MMA(s[2 * p + 1], qh[c], bl[2], bl[3]);
            }
        }

        // ---- online softmax (row r = lane/4 and r+8) ----
        float mx0 = -1e30f, mx1 = -1e30f;
#pragma unroll
        for (int j = 0; j < 8; j++) {
            mx0 = fmaxf(mx0, fmaxf(s[j][0], s[j][1]));
            mx1 = fmaxf(mx1, fmaxf(s[j][2], s[j][3]));
        }
        mx0 = fmaxf(mx0, __shfl_xor_sync(0xffffffffu, mx0, 1));
        mx0 = fmaxf(mx0, __shfl_xor_sync(0xffffffffu, mx0, 2));
        mx1 = fmaxf(mx1, __shfl_xor_sync(0xffffffffu, mx1, 1));
        mx1 = fmaxf(mx1, __shfl_xor_sync(0xffffffffu, mx1, 2));
        const float M0 = fmaxf(m0, mx0), M1 = fmaxf(m1, mx1);
        const float c0 = ex2f((m0 - M0) * L2E), c1 = ex2f((m1 - M1) * L2E);
        const float z0 = M0 * L2E, z1 = M1 * L2E;
        m0 = M0; m1 = M1;

        float rs0 = 0.f, rs1 = 0.f;
        uint32_t pah[4][4], pal[4][4];
#pragma unroll
        for (int c = 0; c < 4; c++) {
            float p00 = ex2f(fmaf(s[2 * c][0], L2E, -z0));
            float p01 = ex2f(fmaf(s[2 * c][1], L2E, -z0));
            float p02 = ex2f(fmaf(s[2 * c][2], L2E, -z1));
            float p03 = ex2f(fmaf(s[2 * c][3], L2E, -z1));
            float p10 = ex2f(fmaf(s[2 * c + 1][0], L2E, -z0));
            float p11 = ex2f(fmaf(s[2 * c + 1][1], L2E, -z0));
            float p12 = ex2f(fmaf(s[2 * c + 1][2], L2E, -z1));
            float p13 = ex2f(fmaf(s[2 * c + 1][3], L2E, -z1));
            rs0 += p00 + p01 + p10 + p11;
            rs1 += p02 + p03 + p12 + p13;
            pah[c][0] = packbf(p00, p01);
            pah[c][1] = packbf(p02, p03);
            pah[c][2] = packbf(p10, p11);
            pah[c][3] = packbf(p12, p13);
#pragma unroll
            for (int k = 0; k < 4; k++) {
                float hl = __uint_as_float(pah[c][k] << 16);
                float hh = __uint_as_float(pah[c][k] & 0xFFFF0000u);
                float e0 = (k == 0 ? p00 : k == 1 ? p02 : k == 2 ? p10 : p12) - hl;
                float e1 = (k == 0 ? p01 : k == 1 ? p03 : k == 2 ? p11 : p13) - hh;
                pal[c][k] = packbf(e0, e1);
            }
        }
        // FIX (R5 inf): each lane only holds 16 of 64 columns per row —
        // the row sum must be quad-reduced like the max, or l is partial
        // (and frequently exactly 0 on near-hardmax rows -> 1/0 = inf).
        rs0 += __shfl_xor_sync(0xffffffffu, rs0, 1);
        rs0 += __shfl_xor_sync(0xffffffffu, rs0, 2);
        rs1 += __shfl_xor_sync(0xffffffffu, rs1, 1);
        rs1 += __shfl_xor_sync(0xffffffffu, rs1, 2);
        l0 = l0 * c0 + rs0;
        l1 = l1 * c1 + rs1;
#pragma unroll
        for (int j = 0; j < 8; j++) {
            o[j][0] *= c0; o[j][1] *= c0;
            o[j][2] *= c1; o[j][3] *= c1;
        }

        // ---- O += P V : ph*vh + pl*vh + ph*vl ----
        const uint32_t vbH = sb + OVH + buf * BN * ROWB;
        const uint32_t vbL = sb + OVL + buf * BN * ROWB;
#pragma unroll
        for (int c = 0; c < 4; c++) {
#pragma unroll
            for (int p = 0; p < 4; p++) {
                uint32_t b[4], bl[4];
                uint32_t ra = (uint32_t)((c * 16 + vrow) * ROWB + p * 32 + vbyt);
                LDSM4T(b, vbH + ra);
                LDSM4T(bl, vbL + ra);
                MMA(o[2 * p],     pah[c], b[0], b[1]);
                MMA(o[2 * p + 1], pah[c], b[2], b[3]);
                MMA(o[2 * p],     pal[c], b[0], b[1]);
                MMA(o[2 * p + 1], pal[c], b[2], b[3]);
                MMA(o[2 * p],     pah[c], bl[0], bl[1]);
                MMA(o[2 * p + 1], pah[c], bl[2], bl[3]);
            }
        }
        if (t + 1 < NT) { CP_WAIT0(); __syncthreads(); }
    }

    // ---- epilogue: write partial O, m, l ----
    const int r0 = qbase + wid * 16 + (lane >> 2);
    const int r1 = r0 + 8;
    const int col = (lane & 3) * 2;
    size_t b0 = ((size_t)blockIdx.y * SEQ + r0) * DIM;
    size_t b1 = ((size_t)blockIdx.y * SEQ + r1) * DIM;
#pragma unroll
    for (int j = 0; j < 8; j++) {
        float2 v0 = make_float2(o[j][0], o[j][1]);
        float2 v1 = make_float2(o[j][2], o[j][3]);
        *(float2*)&g_Op[b0 + j * 8 + col] = v0;
        *(float2*)&g_Op[b1 + j * 8 + col] = v1;
    }
    if ((lane & 3) == 0) {
        g_m[blockIdx.y * SEQ + r0] = m0;
        g_m[blockIdx.y * SEQ + r1] = m1;
        g_l[blockIdx.y * SEQ + r0] = l0;
        g_l[blockIdx.y * SEQ + r1] = l1;
    }
}

// -------- merge the 2 KV-split partials --------
__global__ __launch_bounds__(256, 1) void merge_kernel(float* __restrict__ out) {
    int e = (blockIdx.x * 256 + threadIdx.x) * 4;
    int s = e / DIM;
    float m0 = g_m[s], m1 = g_m[SEQ + s];
    float M = fmaxf(m0, m1);
    float w0 = ex2f((m0 - M) * L2E), w1 = ex2f((m1 - M) * L2E);
    float inv = 1.f / (w0 * g_l[s] + w1 * g_l[SEQ + s]);
    float4 a = *(const float4*)&g_Op[e];
    float4 b = *(const float4*)&g_Op[SEQ * DIM + e];
    float4 r;
    r.x = (w0 * a.x + w1 * b.x) * inv;
    r.y = (w0 * a.y + w1 * b.y) * inv;
    r.z = (w0 * a.z + w1 * b.z) * inv;
    r.w = (w0 * a.w + w1 * b.w) * inv;
    *(float4*)&out[e] = r;
}

// -------- QKV projection (fp32 FFMA) + bf16 hi/lo split, row-major --------
__global__ __launch_bounds__(256, 1) void qkv_kernel(
    const float* __restrict__ X, const float* __restrict__ WQ,
    const float* __restrict__ WK, const float* __restrict__ WV)
{
    __shared__ float Xs[64][17];
    __shared__ float Ws[16][68];

    const int tid = threadIdx.x;
    const int tx = tid & 15, ty = tid >> 4;
    const int mbase = blockIdx.x * 64;
    const int w = blockIdx.y;
    const float* __restrict__ W = (w == 0) ? WQ : ((w == 1) ? WK : WV);

    const int xr = tid >> 2, xc = (tid & 3) << 2;
    const int wr = tid >> 4, wc = (tid & 15) << 2;

    float acc[4][4];
#pragma unroll
    for (int i = 0; i < 4; i++)
#pragma unroll
        for (int j = 0; j < 4; j++) acc[i][j] = 0.f;

    for (int kb = 0; kb < EMB; kb += 16) {
        float4 xv = *(const float4*)(X + (mbase + xr) * EMB + kb + xc);
        Xs[xr][xc] = xv.x; Xs[xr][xc + 1] = xv.y;
        Xs[xr][xc + 2] = xv.z; Xs[xr][xc + 3] = xv.w;
        *(float4*)&Ws[wr][wc] = *(const float4*)(W + (kb + wr) * DIM + wc);
        __syncthreads();
#pragma unroll
        for (int k = 0; k < 16; k++) {
            float a[4];
#pragma unroll
            for (int i = 0; i < 4; i++) a[i] = Xs[4 * ty + i][k];
            float4 b4 = *(const float4*)&Ws[k][4 * tx];
            const float* b = (const float*)&b4;
#pragma unroll
            for (int i = 0; i < 4; i++)
#pragma unroll
                for (int j = 0; j < 4; j++) acc[i][j] += a[i] * b[j];
        }
        __syncthreads();
    }

    const float scale = (w == 0) ? 0.125f : 1.0f;
    __nv_bfloat16* dh = (w == 0) ? g_Qh : ((w == 1) ? g_Kh : g_Vh);
    __nv_bfloat16* dl = (w == 0) ? g_Ql : ((w == 1) ? g_Kl : g_Vl);
#pragma unroll
    for (int i = 0; i < 4; i++) {
        float v0 = acc[i][0] * scale, v1 = acc[i][1] * scale;
        float v2 = acc[i][2] * scale, v3 = acc[i][3] * scale;
        uint32_t h01 = packbf(v0, v1), h23 = packbf(v2, v3);
        uint32_t lo01 = packbf(v0 - __uint_as_float(h01 << 16),
                               v1 - __uint_as_float(h01 & 0xFFFF0000u));
        uint32_t lo23 = packbf(v2 - __uint_as_float(h23 << 16),
                               v3 - __uint_as_float(h23 & 0xFFFF0000u));
        size_t idx = (size_t)(mbase + 4 * ty + i) * DIM + 4 * tx;
        *(uint2*)&dh[idx] = make_uint2(h01, h23);
        *(uint2*)&dl[idx] = make_uint2(lo01, lo23);
    }
}

extern "C" void kernel_launch(void* const* d_in, const int* in_sizes, int n_in,
                              void* d_out, int out_size)
{
    const float* X  = (const float*)d_in[0];
    const float* WQ = (const float*)d_in[1];
    const float* WK = (const float*)d_in[2];
    const float* WV = (const float*)d_in[3];
    float* out = (float*)d_out;

    cudaFuncSetAttribute(attn_kernel,
                         cudaFuncAttributeMaxDynamicSharedMemorySize, SMEM_BYTES);

    dim3 g1(SEQ / 64, 3);
    qkv_kernel<<<g1, 256>>>(X, WQ, WK, WV);
    dim3 ga(SEQ / BM, NSPLIT);
    attn_kernel<<<ga, 256, SMEM_BYTES>>>();
    merge_kernel<<<SEQ * DIM / 1024, 256>>>(out);
}

// round 12
// speedup vs baseline: 3.3590x; 1.0605x over previous
#include <cuda_runtime.h>
#include <cuda_bf16.h>
#include <cstdint>

#define SEQ 8192
#define EMB 768
#define DIM 64
#define BM 128
#define BN 64
#define NSPLIT 2
#define KVPER (SEQ / NSPLIT)
#define NT (KVPER / BN)
#define L2E 1.4426950408889634f
#define ROWB 144   // padded smem row bytes (64 bf16 = 128B data + 16B pad)

__device__ __nv_bfloat16 g_Qh[SEQ * DIM], g_Ql[SEQ * DIM];
__device__ __nv_bfloat16 g_Kh[SEQ * DIM], g_Kl[SEQ * DIM];
__device__ __nv_bfloat16 g_Vh[SEQ * DIM], g_Vl[SEQ * DIM];
__device__ float g_Op[NSPLIT * SEQ * DIM];
__device__ float g_m[NSPLIT * SEQ], g_l[NSPLIT * SEQ];

__device__ __forceinline__ uint32_t smem_u32(const void* p) {
    uint32_t a;
    asm("{ .reg .u64 t; cvta.to.shared.u64 t, %1; cvt.u32.u64 %0, t; }" : "=r"(a) : "l"(p));
    return a;
}
__device__ __forceinline__ float ex2f(float x) {
    float y; asm("ex2.approx.ftz.f32 %0, %1;" : "=f"(y) : "f"(x)); return y;
}
__device__ __forceinline__ void cpa16(uint32_t dst, const void* src) {
    asm volatile("cp.async.cg.shared.global [%0], [%1], 16;" :: "r"(dst), "l"(src));
}
#define CP_COMMIT() asm volatile("cp.async.commit_group;" ::: "memory")
#define CP_WAIT0()  asm volatile("cp.async.wait_group 0;" ::: "memory")
#define CP_WAIT1()  asm volatile("cp.async.wait_group 1;" ::: "memory")

__device__ __forceinline__ uint32_t packbf(float lo, float hi) {
    uint32_t r; asm("cvt.rn.bf16x2.f32 %0, %1, %2;" : "=r"(r) : "f"(hi), "f"(lo)); return r;
}
__device__ __forceinline__ uint32_t totf(float x) {
    uint32_t r; asm("cvt.rna.tf32.f32 %0, %1;" : "=r"(r) : "f"(x)); return r;
}

#define LDSM4(r, a) asm volatile( \
    "ldmatrix.sync.aligned.m8n8.x4.shared.b16 {%0,%1,%2,%3}, [%4];" \
    : "=r"((r)[0]), "=r"((r)[1]), "=r"((r)[2]), "=r"((r)[3]) : "r"(a))
#define LDSM4T(r, a) asm volatile( \
    "ldmatrix.sync.aligned.m8n8.x4.trans.shared.b16 {%0,%1,%2,%3}, [%4];" \
    : "=r"((r)[0]), "=r"((r)[1]), "=r"((r)[2]), "=r"((r)[3]) : "r"(a))
#define MMA(d, a, b0, b1) asm volatile( \
    "mma.sync.aligned.m16n8k16.row.col.f32.bf16.bf16.f32 " \
    "{%0,%1,%2,%3}, {%4,%5,%6,%7}, {%8,%9}, {%0,%1,%2,%3};" \
    : "+f"((d)[0]), "+f"((d)[1]), "+f"((d)[2]), "+f"((d)[3]) \
    : "r"((a)[0]), "r"((a)[1]), "r"((a)[2]), "r"((a)[3]), "r"(b0), "r"(b1))
#define MMAT(d, a, b0, b1) asm volatile( \
    "mma.sync.aligned.m16n8k8.row.col.f32.tf32.tf32.f32 " \
    "{%0,%1,%2,%3}, {%4,%5,%6,%7}, {%8,%9}, {%0,%1,%2,%3};" \
    : "+f"((d)[0]), "+f"((d)[1]), "+f"((d)[2]), "+f"((d)[3]) \
    : "r"((a)[0]), "r"((a)[1]), "r"((a)[2]), "r"((a)[3]), "r"(b0), "r"(b1))

// smem byte offsets for attn (K/V have 2 buffers of 64*ROWB each)
#define OQH 0
#define OQL (OQH + BM * ROWB)
#define OKH (OQL + BM * ROWB)
#define OKL (OKH + 2 * BN * ROWB)
#define OVH (OKL + 2 * BN * ROWB)
#define OVL (OVH + 2 * BN * ROWB)
#define SMEM_BYTES (OVL + 2 * BN * ROWB)   // 110592

// ---------------------------------------------------------------------------
// Flash attention, FA2-style mma.sync bf16 hi/lo split. (unchanged from R9)
// ---------------------------------------------------------------------------
__global__ __launch_bounds__(256, 1) void attn_kernel() {
    extern __shared__ char dynsm[];
    const int tid = threadIdx.x, lane = tid & 31, wid = tid >> 5;
    const int qbase = blockIdx.x * BM;
    const int kbase = blockIdx.y * KVPER;
    const uint32_t sb = smem_u32(dynsm);

#pragma unroll
    for (int i = 0; i < 4; i++) {
        int c = tid + i * 256;
        uint32_t d = (uint32_t)((c >> 3) * ROWB + (c & 7) * 16);
        size_t sByte = ((size_t)(qbase + (c >> 3)) * DIM) * 2 + (c & 7) * 16;
        cpa16(sb + OQH + d, (const char*)g_Qh + sByte);
        cpa16(sb + OQL + d, (const char*)g_Ql + sByte);
    }
#pragma unroll
    for (int i = 0; i < 2; i++) {
        int c = tid + i * 256;
        uint32_t d = (uint32_t)((c >> 3) * ROWB + (c & 7) * 16);
        size_t sByte = ((size_t)(kbase + (c >> 3)) * DIM) * 2 + (c & 7) * 16;
        cpa16(sb + OKH + d, (const char*)g_Kh + sByte);
        cpa16(sb + OKL + d, (const char*)g_Kl + sByte);
        cpa16(sb + OVH + d, (const char*)g_Vh + sByte);
        cpa16(sb + OVL + d, (const char*)g_Vl + sByte);
    }
    CP_COMMIT(); CP_WAIT0();
    __syncthreads();

    uint32_t qh[4][4], ql[4][4];
    {
        uint32_t r = (uint32_t)(wid * 16 + (lane & 15));
        uint32_t bo = ((lane >> 4) & 1) << 4;
#pragma unroll
        for (int c = 0; c < 4; c++) {
            LDSM4(qh[c], sb + OQH + r * ROWB + c * 32 + bo);
            LDSM4(ql[c], sb + OQL + r * ROWB + c * 32 + bo);
        }
    }

    float o[8][4];
#pragma unroll
    for (int j = 0; j < 8; j++)
#pragma unroll
        for (int k = 0; k < 4; k++) o[j][k] = 0.f;
    float m0 = -1e30f, m1 = -1e30f, l0 = 0.f, l1 = 0.f;

    const int krow = (lane & 7) + ((lane & 16) ? 8 : 0);
    const int kbyt = (lane & 8) ? 16 : 0;
    const int vrow = (lane & 7) + ((lane & 8) ? 8 : 0);
    const int vbyt = (lane & 16) ? 16 : 0;

    for (int t = 0; t < NT; t++) {
        const int buf = t & 1, nb = buf ^ 1;
        if (t + 1 < NT) {
            int kr = kbase + (t + 1) * BN;
#pragma unroll
            for (int i = 0; i < 2; i++) {
                int c = tid + i * 256;
                uint32_t d = (uint32_t)(nb * BN * ROWB + (c >> 3) * ROWB + (c & 7) * 16);
                size_t sByte = ((size_t)(kr + (c >> 3)) * DIM) * 2 + (c & 7) * 16;
                cpa16(sb + OKH + d, (const char*)g_Kh + sByte);
                cpa16(sb + OKL + d, (const char*)g_Kl + sByte);
                cpa16(sb + OVH + d, (const char*)g_Vh + sByte);
                cpa16(sb + OVL + d, (const char*)g_Vl + sByte);
            }
            CP_COMMIT();
        }

        float s[8][4];
#pragma unroll
        for (int j = 0; j < 8; j++)
#pragma unroll
            for (int k = 0; k < 4; k++) s[j][k] = 0.f;
        const uint32_t kbH = sb + OKH + buf * BN * ROWB;
        const uint32_t kbL = sb + OKL + buf * BN * ROWB;
#pragma unroll
        for (int c = 0; c < 4; c++) {
#pragma unroll
            for (int p = 0; p < 4; p++) {
                uint32_t b[4], bl[4];
                uint32_t ra = (uint32_t)((p * 16 + krow) * ROWB + c * 32 + kbyt);
                LDSM4(b, kbH + ra);
                LDSM4(bl, kbL + ra);
                MMA(s[2 * p],     qh[c], b[0], b[1]);
                MMA(s[2 * p + 1], qh[c], b[2], b[3]);
                MMA(s[2 * p],     ql[c], b[0], b[1]);
                MMA(s[2 * p + 1], ql[c], b[2], b[3]);
                MMA(s[2 * p],     qh[c], bl[0], bl[1]);
                MMA(s[2 * p + 1], qh[c], bl[2], bl[3]);
            }
        }

        float mx0 = -1e30f, mx1 = -1e30f;
#pragma unroll
        for (int j = 0; j < 8; j++) {
            mx0 = fmaxf(mx0, fmaxf(s[j][0], s[j][1]));
            mx1 = fmaxf(mx1, fmaxf(s[j][2], s[j][3]));
        }
        mx0 = fmaxf(mx0, __shfl_xor_sync(0xffffffffu, mx0, 1));
        mx0 = fmaxf(mx0, __shfl_xor_sync(0xffffffffu, mx0, 2));
        mx1 = fmaxf(mx1, __shfl_xor_sync(0xffffffffu, mx1, 1));
        mx1 = fmaxf(mx1, __shfl_xor_sync(0xffffffffu, mx1, 2));
        const float M0 = fmaxf(m0, mx0), M1 = fmaxf(m1, mx1);
        const float c0 = ex2f((m0 - M0) * L2E), c1 = ex2f((m1 - M1) * L2E);
        const float z0 = M0 * L2E, z1 = M1 * L2E;
        m0 = M0; m1 = M1;

        float rs0 = 0.f, rs1 = 0.f;
        uint32_t pah[4][4], pal[4][4];
#pragma unroll
        for (int c = 0; c < 4; c++) {
            float p00 = ex2f(fmaf(s[2 * c][0], L2E, -z0));
            float p01 = ex2f(fmaf(s[2 * c][1], L2E, -z0));
            float p02 = ex2f(fmaf(s[2 * c][2], L2E, -z1));
            float p03 = ex2f(fmaf(s[2 * c][3], L2E, -z1));
            float p10 = ex2f(fmaf(s[2 * c + 1][0], L2E, -z0));
            float p11 = ex2f(fmaf(s[2 * c + 1][1], L2E, -z0));
            float p12 = ex2f(fmaf(s[2 * c + 1][2], L2E, -z1));
            float p13 = ex2f(fmaf(s[2 * c + 1][3], L2E, -z1));
            rs0 += p00 + p01 + p10 + p11;
            rs1 += p02 + p03 + p12 + p13;
            pah[c][0] = packbf(p00, p01);
            pah[c][1] = packbf(p02, p03);
            pah[c][2] = packbf(p10, p11);
            pah[c][3] = packbf(p12, p13);
#pragma unroll
            for (int k = 0; k < 4; k++) {
                float hl = __uint_as_float(pah[c][k] << 16);
                float hh = __uint_as_float(pah[c][k] & 0xFFFF0000u);
                float e0 = (k == 0 ? p00 : k == 1 ? p02 : k == 2 ? p10 : p12) - hl;
                float e1 = (k == 0 ? p01 : k == 1 ? p03 : k == 2 ? p11 : p13) - hh;
                pal[c][k] = packbf(e0, e1);
            }
        }
        rs0 += __shfl_xor_sync(0xffffffffu, rs0, 1);
        rs0 += __shfl_xor_sync(0xffffffffu, rs0, 2);
        rs1 += __shfl_xor_sync(0xffffffffu, rs1, 1);
        rs1 += __shfl_xor_sync(0xffffffffu, rs1, 2);
        l0 = l0 * c0 + rs0;
        l1 = l1 * c1 + rs1;
#pragma unroll
        for (int j = 0; j < 8; j++) {
            o[j][0] *= c0; o[j][1] *= c0;
            o[j][2] *= c1; o[j][3] *= c1;
        }

        const uint32_t vbH = sb + OVH + buf * BN * ROWB;
        const uint32_t vbL = sb + OVL + buf * BN * ROWB;
#pragma unroll
        for (int c = 0; c < 4; c++) {
#pragma unroll
            for (int p = 0; p < 4; p++) {
                uint32_t b[4], bl[4];
                uint32_t ra = (uint32_t)((c * 16 + vrow) * ROWB + p * 32 + vbyt);
                LDSM4T(b, vbH + ra);
                LDSM4T(bl, vbL + ra);
                MMA(o[2 * p],     pah[c], b[0], b[1]);
                MMA(o[2 * p + 1], pah[c], b[2], b[3]);
                MMA(o[2 * p],     pal[c], b[0], b[1]);
                MMA(o[2 * p + 1], pal[c], b[2], b[3]);
                MMA(o[2 * p],     pah[c], bl[0], bl[1]);
                MMA(o[2 * p + 1], pah[c], bl[2], bl[3]);
            }
        }
        if (t + 1 < NT) { CP_WAIT0(); __syncthreads(); }
    }

    const int r0 = qbase + wid * 16 + (lane >> 2);
    const int r1 = r0 + 8;
    const int col = (lane & 3) * 2;
    size_t b0 = ((size_t)blockIdx.y * SEQ + r0) * DIM;
    size_t b1 = ((size_t)blockIdx.y * SEQ + r1) * DIM;
#pragma unroll
    for (int j = 0; j < 8; j++) {
        *(float2*)&g_Op[b0 + j * 8 + col] = make_float2(o[j][0], o[j][1]);
        *(float2*)&g_Op[b1 + j * 8 + col] = make_float2(o[j][2], o[j][3]);
    }
    if ((lane & 3) == 0) {
        g_m[blockIdx.y * SEQ + r0] = m0;
        g_m[blockIdx.y * SEQ + r1] = m1;
        g_l[blockIdx.y * SEQ + r0] = l0;
        g_l[blockIdx.y * SEQ + r1] = l1;
    }
}

// -------- merge the 2 KV-split partials (unchanged) --------
__global__ __launch_bounds__(256, 1) void merge_kernel(float* __restrict__ out) {
    int e = (blockIdx.x * 256 + threadIdx.x) * 4;
    int s = e / DIM;
    float m0 = g_m[s], m1 = g_m[SEQ + s];
    float M = fmaxf(m0, m1);
    float w0 = ex2f((m0 - M) * L2E), w1 = ex2f((m1 - M) * L2E);
    float inv = 1.f / (w0 * g_l[s] + w1 * g_l[SEQ + s]);
    float4 a = *(const float4*)&g_Op[e];
    float4 b = *(const float4*)&g_Op[SEQ * DIM + e];
    float4 r;
    r.x = (w0 * a.x + w1 * b.x) * inv;
    r.y = (w0 * a.y + w1 * b.y) * inv;
    r.z = (w0 * a.z + w1 * b.z) * inv;
    r.w = (w0 * a.w + w1 * b.w) * inv;
    *(float4*)&out[e] = r;
}

// ---------------------------------------------------------------------------
// QKV projection on tensor cores: 3-term tf32 split (xh*wh + xl*wh + xh*wl).
// grid (64, 3), 128 threads = 4 warps; warp w owns rows w*32..w*32+31, N=64.
// FIX (R10, rel_err 1.4e-2): single-term tf32 leaves ~2^-11 operand error ->
// ~0.3 logit error on near-hardmax rows. The split drops it to ~2^-22.
// ---------------------------------------------------------------------------
#define QBM 128
#define QBK 32
#define NSTG (EMB / QBK)   // 24
#define XRB 36             // floats per X smem row (32 data + 4 pad)
#define WRB 72             // floats per W smem row (64 data + 8 pad)
#define QSMEM ((2 * QBM * XRB + 2 * QBK * WRB) * 4)   // 55296 B

__global__ __launch_bounds__(128, 2) void qkv_kernel(
    const float* __restrict__ X, const float* __restrict__ WQ,
    const float* __restrict__ WK, const float* __restrict__ WV)
{
    extern __shared__ float qsm[];
    float* Xs = qsm;                        // [2][QBM*XRB]
    float* Wsm = qsm + 2 * QBM * XRB;       // [2][QBK*WRB]

    const int tid = threadIdx.x, lane = tid & 31, wid = tid >> 5;
    const int mbase = blockIdx.x * QBM;
    const int w = blockIdx.y;
    const float* __restrict__ W = (w == 0) ? WQ : ((w == 1) ? WK : WV);
    const uint32_t xs_u = smem_u32(Xs);
    const uint32_t ws_u = smem_u32(Wsm);

    auto loadstage = [&](int buf, int kb) {
        uint32_t xd = xs_u + (uint32_t)(buf * QBM * XRB * 4);
#pragma unroll
        for (int i = 0; i < 8; i++) {
            int id = tid + i * 128;          // 0..1023
            int r = id >> 3, c = id & 7;
            cpa16(xd + (uint32_t)(r * (XRB * 4) + c * 16),
                  X + (size_t)(mbase + r) * EMB + kb + c * 4);
        }
        uint32_t wd = ws_u + (uint32_t)(buf * QBK * WRB * 4);
#pragma unroll
        for (int i = 0; i < 4; i++) {
            int id = tid + i * 128;          // 0..511
            int r = id >> 4, c = id & 15;
            cpa16(wd + (uint32_t)(r * (WRB * 4) + c * 16),
                  W + (size_t)(kb + r) * DIM + c * 4);
        }
    };

    float acc[2][8][4];
#pragma unroll
    for (int mt = 0; mt < 2; mt++)
#pragma unroll
        for (int nt = 0; nt < 8; nt++)
#pragma unroll
            for (int k = 0; k < 4; k++) acc[mt][nt][k] = 0.f;

    const int a_r = wid * 32 + (lane >> 2);
    const int a_c = lane & 3;
    const int b_n = lane >> 2;

    loadstage(0, 0);
    CP_COMMIT();

    for (int s = 0; s < NSTG; s++) {
        const int buf = s & 1;
        const bool pre = (s + 1 < NSTG);
        if (pre) { loadstage(buf ^ 1, (s + 1) * QBK); CP_COMMIT(); }
        if (pre) CP_WAIT1(); else CP_WAIT0();
        __syncthreads();
        const float* xb = Xs + buf * QBM * XRB;
        const float* wb = Wsm + buf * QBK * WRB;
#pragma unroll
        for (int j = 0; j < 4; j++) {
            uint32_t uah[2][4], ual[2][4], ubh[8][2], ubl[8][2];
#pragma unroll
            for (int mt = 0; mt < 2; mt++) {
                int r0 = a_r + mt * 16;
                int cc = a_c + j * 8;
                float v0 = xb[r0 * XRB + cc];
                float v1 = xb[(r0 + 8) * XRB + cc];
                float v2 = xb[r0 * XRB + cc + 4];
                float v3 = xb[(r0 + 8) * XRB + cc + 4];
                uah[mt][0] = totf(v0); ual[mt][0] = totf(v0 - __uint_as_float(uah[mt][0]));
                uah[mt][1] = totf(v1); ual[mt][1] = totf(v1 - __uint_as_float(uah[mt][1]));
                uah[mt][2] = totf(v2); ual[mt][2] = totf(v2 - __uint_as_float(uah[mt][2]));
                uah[mt][3] = totf(v3); ual[mt][3] = totf(v3 - __uint_as_float(uah[mt][3]));
            }
#pragma unroll
            for (int nt = 0; nt < 8; nt++) {
                int k0 = j * 8 + a_c;
                int n = nt * 8 + b_n;
                float w0 = wb[k0 * WRB + n];
                float w1 = wb[(k0 + 4) * WRB + n];
                ubh[nt][0] = totf(w0); ubl[nt][0] = totf(w0 - __uint_as_float(ubh[nt][0]));
                ubh[nt][1] = totf(w1); ubl[nt][1] = totf(w1 - __uint_as_float(ubh[nt][1]));
            }
#pragma unroll
            for (int mt = 0; mt < 2; mt++)
#pragma unroll
                for (int nt = 0; nt < 8; nt++) {
                    MMAT(acc[mt][nt], uah[mt], ubh[nt][0], ubh[nt][1]);
                    MMAT(acc[mt][nt], ual[mt], ubh[nt][0], ubh[nt][1]);
                    MMAT(acc[mt][nt], uah[mt], ubl[nt][0], ubl[nt][1]);
                }
        }
        __syncthreads();
    }

    // epilogue: scale (Q only) + bf16 hi/lo split + store
    const float scale = (w == 0) ? 0.125f : 1.0f;
    __nv_bfloat16* dh = (w == 0) ? g_Qh : ((w == 1) ? g_Kh : g_Vh);
    __nv_bfloat16* dl = (w == 0) ? g_Ql : ((w == 1) ? g_Kl : g_Vl);
#pragma unroll
    for (int mt = 0; mt < 2; mt++) {
        int r0 = mbase + wid * 32 + mt * 16 + (lane >> 2);
#pragma unroll
        for (int nt = 0; nt < 8; nt++) {
            int col = nt * 8 + (lane & 3) * 2;
            float v0 = acc[mt][nt][0] * scale, v1 = acc[mt][nt][1] * scale;
            uint32_t h = packbf(v0, v1);
            uint32_t lo = packbf(v0 - __uint_as_float(h << 16),
                                 v1 - __uint_as_float(h & 0xFFFF0000u));
            *(uint32_t*)&dh[(size_t)r0 * DIM + col] = h;
            *(uint32_t*)&dl[(size_t)r0 * DIM + col] = lo;
            float v2 = acc[mt][nt][2] * scale, v3 = acc[mt][nt][3] * scale;
            h = packbf(v2, v3);
            lo = packbf(v2 - __uint_as_float(h << 16),
                        v3 - __uint_as_float(h & 0xFFFF0000u));
            *(uint32_t*)&dh[(size_t)(r0 + 8) * DIM + col] = h;
            *(uint32_t*)&dl[(size_t)(r0 + 8) * DIM + col] = lo;
        }
    }
}

extern "C" void kernel_launch(void* const* d_in, const int* in_sizes, int n_in,
                              void* d_out, int out_size)
{
    const float* X  = (const float*)d_in[0];
    const float* WQ = (const float*)d_in[1];
    const float* WK = (const float*)d_in[2];
    const float* WV = (const float*)d_in[3];
    float* out = (float*)d_out;

    cudaFuncSetAttribute(attn_kernel,
                         cudaFuncAttributeMaxDynamicSharedMemorySize, SMEM_BYTES);
    cudaFuncSetAttribute(qkv_kernel,
                         cudaFuncAttributeMaxDynamicSharedMemorySize, QSMEM);

    dim3 g1(SEQ / QBM, 3);
    qkv_kernel<<<g1, 128, QSMEM>>>(X, WQ, WK, WV);
    dim3 ga(SEQ / BM, NSPLIT);
    attn_kernel<<<ga, 256, SMEM_BYTES>>>();
    merge_kernel<<<SEQ * DIM / 1024, 256>>>(out);
}